// round 14
// baseline (speedup 1.0000x reference)
#include <cuda_runtime.h>

#define BB 64
#define WW 128
#define FF 64
#define OUTF 64
#define CH 128
#define TI 16
#define PARTN (BB * WW * OUTF)

typedef unsigned long long ull;

// Per-head partial outputs
__device__ float g_part[2 * PARTN];

// ---- packed f32x2 helpers ----
__device__ __forceinline__ ull fma2(ull a, ull b, ull c) {
    ull d; asm("fma.rn.f32x2 %0, %1, %2, %3;" : "=l"(d) : "l"(a), "l"(b), "l"(c)); return d;
}
__device__ __forceinline__ ull add2(ull a, ull b) {
    ull d; asm("add.rn.f32x2 %0, %1, %2;" : "=l"(d) : "l"(a), "l"(b)); return d;
}
__device__ __forceinline__ float lo2(ull v) { return __uint_as_float((unsigned)(v & 0xffffffffu)); }
__device__ __forceinline__ float hi2(ull v) { return __uint_as_float((unsigned)(v >> 32)); }
__device__ __forceinline__ float hsum2(ull v) { return lo2(v) + hi2(v); }
#define ABSMASK 0x7fffffff7fffffffULL

// 16B-chunk swizzle within a 64-float (16-chunk) row
__device__ __forceinline__ int swz16(int row, int c) { return (c & 8) | ((c ^ row) & 7); }

__device__ __forceinline__ unsigned to_tf32(float v) {
    unsigned o; asm("cvt.rna.tf32.f32 %0, %1;" : "=r"(o) : "f"(v)); return o;
}

__device__ __forceinline__ unsigned smem_u32(const void* p) {
    unsigned a;
    asm("{ .reg .u64 t; cvta.to.shared.u64 t, %1; cvt.u32.u64 %0, t; }"
        : "=r"(a) : "l"(p));
    return a;
}
__device__ __forceinline__ void cp_async16(unsigned dst_smem, const void* src) {
    asm volatile("cp.async.cg.shared.global [%0], [%1], 16;"
                 :: "r"(dst_smem), "l"(src) : "memory");
}
__device__ __forceinline__ void cp_async_commit_wait_all() {
    asm volatile("cp.async.commit_group;" ::: "memory");
    asm volatile("cp.async.wait_group 0;" ::: "memory");
}

#define MMA_TF32(acc, a0, a1, a2, a3, b0, b1) \
    asm("mma.sync.aligned.m16n8k8.row.col.f32.tf32.tf32.f32 " \
        "{%0,%1,%2,%3}, {%4,%5,%6,%7}, {%8,%9}, {%0,%1,%2,%3};" \
        : "+f"((acc)[0]), "+f"((acc)[1]), "+f"((acc)[2]), "+f"((acc)[3]) \
        : "r"(a0), "r"(a1), "r"(a2), "r"(a3), "r"(b0), "r"(b1))

// ---------------------------------------------------------------------------
// Fused kernel: projections (tf32 MMA) + GATv2 attention, per (i-tile, b, h).
// grid (8, 64, 2), 256 threads, 4 blocks/SM target.
// smem (floats), phased reuse:
//   xsm   [128 x 68] X[b] fp32        0 .. 8704   -> fsrc [128x64] swizzled fp32
//   wsm   [64 x 68]  W tf32        8704 .. 13056  -> alphaT [16 x 132]
//   xdsm  [16 x 68]  X-dst fp32   13056 .. 14144  -> fdst [16 x 68] fp32
//   a04   [64]                    14144
//   sA    [128]                   14208
//   dA    [16]                    14336
// ---------------------------------------------------------------------------
#define OFF_WSM   8704
#define OFF_XDSM  13056
#define OFF_A04   14144
#define OFF_SA    14208
#define OFF_DA    14336
#define SM_FLOATS 14352
#define SM_BYTES  (SM_FLOATS * 4)

__global__ __launch_bounds__(256, 4) void attn_kernel(
    const float* __restrict__ x,
    const float* __restrict__ w_src, const float* __restrict__ b_src,
    const float* __restrict__ w_dst, const float* __restrict__ b_dst,
    const float* __restrict__ attn_w)
{
    extern __shared__ float sm[];
    float*    xsm    = sm;                       // -> fssm (swizzled fsrc)
    unsigned* wsm    = (unsigned*)(sm + OFF_WSM);
    float*    xdsm   = sm + OFF_XDSM;            // -> fdsm
    float*    a04    = sm + OFF_A04;
    float*    sA     = sm + OFF_SA;
    float*    dA     = sm + OFF_DA;
    unsigned* alphaT = (unsigned*)(sm + OFF_WSM);

    const int tid = threadIdx.x;
    const int b  = blockIdx.y;
    const int i0 = blockIdx.x * TI;
    const int h  = blockIdx.z;

    const int w    = tid >> 5;
    const int lane = tid & 31;
    const int ly = lane >> 2;     // 0..7
    const int lx = lane & 3;      // 0..3

    // ================= Phase 0: fill =================
    // X[b]: 128 rows x 16 chunks -> xsm (plain pad-68)
    {
        const float4* __restrict__ xg4 = (const float4*)(x + b * WW * FF);
        #pragma unroll
        for (int t = 0; t < 8; t++) {
            int m = tid + 256 * t;           // 2048 chunks
            int j = m >> 4, c = m & 15;
            cp_async16(smem_u32(xsm + j * 68 + c * 4), xg4 + j * 16 + c);
        }
        // X-dst rows: 16 x 16 chunks -> xdsm
        int i = tid >> 4, c = tid & 15;
        cp_async16(smem_u32(xdsm + i * 68 + c * 4),
                   (const float4*)(x + (b * WW + i0 + i) * FF) + c);
    }
    // W_src_h: staged LDG + cvt.rna + STS (tf32)
    {
        const float4* __restrict__ wg4 = (const float4*)(w_src + h * 64 * FF);
        #pragma unroll
        for (int t = 0; t < 4; t++) {
            int m = tid + 256 * t;           // 1024 float4
            int r = m >> 4, c4 = m & 15;
            float4 v = wg4[m];
            uint4 u;
            u.x = to_tf32(v.x); u.y = to_tf32(v.y);
            u.z = to_tf32(v.z); u.w = to_tf32(v.w);
            *(uint4*)(wsm + r * 68 + c4 * 4) = u;
        }
    }
    if (tid < 64) a04[tid] = 0.4f * attn_w[h * 64 + tid];
    cp_async_commit_wait_all();
    __syncthreads();

    // ================= Phase 1: fsrc MMAs (X @ W_src_h^T) =================
    // warp w: rows [w*16, +16), all 64 cols, k=64
    float accS[8][4];
    #pragma unroll
    for (int t = 0; t < 8; t++)
        #pragma unroll
        for (int q = 0; q < 4; q++) accS[t][q] = 0.0f;
    {
        const int m0 = w * 16;
        #pragma unroll
        for (int k0 = 0; k0 < 64; k0 += 8) {
            unsigned a0 = to_tf32(xsm[(m0 + ly) * 68 + k0 + lx]);
            unsigned a1 = to_tf32(xsm[(m0 + ly + 8) * 68 + k0 + lx]);
            unsigned a2 = to_tf32(xsm[(m0 + ly) * 68 + k0 + lx + 4]);
            unsigned a3 = to_tf32(xsm[(m0 + ly + 8) * 68 + k0 + lx + 4]);
            #pragma unroll
            for (int t = 0; t < 8; t++) {
                unsigned b0 = wsm[(t * 8 + ly) * 68 + k0 + lx];
                unsigned b1 = wsm[(t * 8 + ly) * 68 + k0 + lx + 4];
                MMA_TF32(accS[t], a0, a1, a2, a3, b0, b1);
            }
        }
    }
    __syncthreads();   // all xsm/wsm reads done

    // ---- refill wsm with W_dst_h; STS fsrc (+bias) swizzled into xsm ----
    {
        const float4* __restrict__ wg4 = (const float4*)(w_dst + h * 64 * FF);
        #pragma unroll
        for (int t = 0; t < 4; t++) {
            int m = tid + 256 * t;
            int r = m >> 4, c4 = m & 15;
            float4 v = wg4[m];
            uint4 u;
            u.x = to_tf32(v.x); u.y = to_tf32(v.y);
            u.z = to_tf32(v.z); u.w = to_tf32(v.w);
            *(uint4*)(wsm + r * 68 + c4 * 4) = u;
        }
    }
    {
        const int m0 = w * 16;
        int jA = m0 + ly, jB = m0 + ly + 8;
        #pragma unroll
        for (int t = 0; t < 8; t++) {
            int c = t * 8 + 2 * lx;                      // even
            float2 bias = *(const float2*)(b_src + h * 64 + c);
            int cc = c >> 2, fr = c & 3;
            *(float2*)(xsm + jA * 64 + swz16(jA, cc) * 4 + fr) =
                make_float2(accS[t][0] + bias.x, accS[t][1] + bias.y);
            *(float2*)(xsm + jB * 64 + swz16(jB, cc) * 4 + fr) =
                make_float2(accS[t][2] + bias.x, accS[t][3] + bias.y);
        }
    }
    __syncthreads();   // W_dst + fsrc visible

    // ================= Phase 2: fdst MMAs (X_dst @ W_dst_h^T) =================
    // warp w: all 16 rows, cols [w*8, +8), k=64
    float accD[4];
    accD[0] = accD[1] = accD[2] = accD[3] = 0.0f;
    {
        const int n0 = w * 8;
        #pragma unroll
        for (int k0 = 0; k0 < 64; k0 += 8) {
            unsigned a0 = to_tf32(xdsm[ly * 68 + k0 + lx]);
            unsigned a1 = to_tf32(xdsm[(ly + 8) * 68 + k0 + lx]);
            unsigned a2 = to_tf32(xdsm[ly * 68 + k0 + lx + 4]);
            unsigned a3 = to_tf32(xdsm[(ly + 8) * 68 + k0 + lx + 4]);
            unsigned b0 = wsm[(n0 + ly) * 68 + k0 + lx];
            unsigned b1 = wsm[(n0 + ly) * 68 + k0 + lx + 4];
            MMA_TF32(accD, a0, a1, a2, a3, b0, b1);
        }
    }
    __syncthreads();   // all xdsm reads done
    {
        const int n0 = w * 8;
        int c = n0 + 2 * lx;
        float2 bias = *(const float2*)(b_dst + h * 64 + c);
        *(float2*)(xdsm + ly * 68 + c) =
            make_float2(accD[0] + bias.x, accD[1] + bias.y);
        *(float2*)(xdsm + (ly + 8) * 68 + c) =
            make_float2(accD[2] + bias.x, accD[3] + bias.y);
    }
    __syncthreads();   // fdst visible

    float* fssm = xsm;            // fsrc, swizzled [128 x 64]
    float* fdsm = xdsm;           // fdst, [16 x 68]
    ulonglong2* fs16 = (ulonglong2*)fssm;

    // ================= Phase 3: per-node dots =================
    if (tid < 128) {               // sA[j]
        int j = tid;
        const ulonglong2* a16 = (const ulonglong2*)a04;
        ull acc = 0ULL;
        #pragma unroll
        for (int f4 = 0; f4 < 16; f4++) {
            ulonglong2 sv = fs16[j * 16 + swz16(j, f4)];
            ulonglong2 av = a16[f4];
            acc = fma2(av.x, sv.x, acc);
            acc = fma2(av.y, sv.y, acc);
        }
        sA[j] = 1.5f * hsum2(acc);
    } else if (tid < 144) {        // dA[i]
        int il = tid - 128;
        const ulonglong2* d16 = (const ulonglong2*)(fdsm + il * 68);
        const ulonglong2* a16 = (const ulonglong2*)a04;
        ull acc = 0ULL;
        #pragma unroll
        for (int f4 = 0; f4 < 16; f4++) {
            ulonglong2 dv = d16[f4];
            ulonglong2 av = a16[f4];
            acc = fma2(av.x, dv.x, acc);
            acc = fma2(av.y, dv.y, acc);
        }
        dA[il] = 1.5f * hsum2(acc);
    }
    __syncthreads();

    // ================= Phase 4: score =================
    const int jt = tid & 31;

    ull acc2[2][4];
    #pragma unroll
    for (int r = 0; r < 2; r++)
        #pragma unroll
        for (int c = 0; c < 4; c++) acc2[r][c] = 0ULL;

    {
        const ulonglong2* a16 = (const ulonglong2*)a04;
        #pragma unroll 4
        for (int f4 = 0; f4 < 16; f4++) {
            ulonglong2 av = a16[f4];
            ulonglong2 dv[2], sv[4];
            dv[0] = *(const ulonglong2*)(fdsm + w * 68 + f4 * 4);
            dv[1] = *(const ulonglong2*)(fdsm + (w + 8) * 68 + f4 * 4);
            int cs = swz16(jt, f4);
            #pragma unroll
            for (int c = 0; c < 4; c++)
                sv[c] = fs16[(jt + 32 * c) * 16 + cs];
            #pragma unroll
            for (int r = 0; r < 2; r++)
                #pragma unroll
                for (int c = 0; c < 4; c++) {
                    ull t0 = add2(sv[c].x, dv[r].x) & ABSMASK;
                    acc2[r][c] = fma2(av.x, t0, acc2[r][c]);
                    ull t1 = add2(sv[c].y, dv[r].y) & ABSMASK;
                    acc2[r][c] = fma2(av.y, t1, acc2[r][c]);
                }
        }
    }

    // ================= Phase 5: softmax -> alphaT (overlays wsm) =========
    __syncthreads();               // fdsm reads done... (alphaT != fdsm, but
                                   // wsm overlay: W_dst reads finished phase 2)
    {
        float sAv[4];
        #pragma unroll
        for (int c = 0; c < 4; c++) sAv[c] = sA[jt + 32 * c];

        #pragma unroll
        for (int r = 0; r < 2; r++) {
            int il = w + 8 * r;
            float dv = dA[il];
            float p[4], ssum = 0.0f;
            #pragma unroll
            for (int c = 0; c < 4; c++) {
                p[c] = __expf(sAv[c] + dv + hsum2(acc2[r][c]));
                ssum += p[c];
            }
            #pragma unroll
            for (int off = 16; off > 0; off >>= 1)
                ssum += __shfl_xor_sync(0xffffffffu, ssum, off);

            float inv = 1.0f / ssum;
            #pragma unroll
            for (int c = 0; c < 4; c++)
                alphaT[il * 132 + jt + 32 * c] = to_tf32(p[c] * inv);
        }
    }
    __syncthreads();

    // ================= Phase 6: aggregation via tf32 MMA =================
    {
        const int n0 = w * 8;
        float acc[4];
        acc[0] = acc[1] = acc[2] = acc[3] = 0.0f;

        const int f  = n0 + ly;
        const int cc = f >> 2;
        const int fr = f & 3;

        #pragma unroll
        for (int k0 = 0; k0 < 128; k0 += 8) {
            unsigned a0 = alphaT[ly * 132 + k0 + lx];
            unsigned a1 = alphaT[(ly + 8) * 132 + k0 + lx];
            unsigned a2 = alphaT[ly * 132 + k0 + lx + 4];
            unsigned a3 = alphaT[(ly + 8) * 132 + k0 + lx + 4];
            int j0 = k0 + lx, j1 = k0 + lx + 4;
            unsigned b0 = to_tf32(fssm[j0 * 64 + swz16(j0, cc) * 4 + fr]);
            unsigned b1 = to_tf32(fssm[j1 * 64 + swz16(j1, cc) * 4 + fr]);
            MMA_TF32(acc, a0, a1, a2, a3, b0, b1);
        }

        float* part = g_part + h * PARTN;
        int iA = i0 + ly;
        *(float2*)(part + (b * WW + iA) * OUTF + n0 + 2 * lx) =
            make_float2(acc[0], acc[1]);
        *(float2*)(part + (b * WW + iA + 8) * OUTF + n0 + 2 * lx) =
            make_float2(acc[2], acc[3]);
    }

#if __CUDA_ARCH__ >= 900
    cudaTriggerProgrammaticLaunchCompletion();
#endif
}

// ---------------------------------------------------------------------------
// Kernel 2: combine heads. out = 0.5 * (part0 + part1). 512 x 256 float4.
// ---------------------------------------------------------------------------
__global__ __launch_bounds__(256) void combine_kernel(float* __restrict__ out)
{
    int m = blockIdx.x * 256 + threadIdx.x;
#if __CUDA_ARCH__ >= 900
    cudaGridDependencySynchronize();
#endif
    const float4* p0 = (const float4*)g_part;
    const float4* p1 = (const float4*)(g_part + PARTN);
    float4 a = p0[m], c = p1[m];
    float4 o;
    o.x = 0.5f * (a.x + c.x);
    o.y = 0.5f * (a.y + c.y);
    o.z = 0.5f * (a.z + c.z);
    o.w = 0.5f * (a.w + c.w);
    ((float4*)out)[m] = o;
}

// ---------------------------------------------------------------------------
extern "C" void kernel_launch(void* const* d_in, const int* in_sizes, int n_in,
                              void* d_out, int out_size)
{
    (void)in_sizes; (void)n_in; (void)out_size;
    const float* x      = (const float*)d_in[0];
    const float* w_src  = (const float*)d_in[1];
    const float* b_src  = (const float*)d_in[2];
    const float* w_dst  = (const float*)d_in[3];
    const float* b_dst  = (const float*)d_in[4];
    const float* attn_w = (const float*)d_in[5];
    float* out = (float*)d_out;

    cudaFuncSetAttribute(attn_kernel,
                         cudaFuncAttributeMaxDynamicSharedMemorySize,
                         SM_BYTES);

    attn_kernel<<<dim3(WW / TI, BB, 2), 256, SM_BYTES>>>(
        x, w_src, b_src, w_dst, b_dst, attn_w);

    // combine with PDL edge to attn
    {
        cudaLaunchAttribute attr[1];
        attr[0].id = cudaLaunchAttributeProgrammaticStreamSerialization;
        attr[0].val.programmaticStreamSerializationAllowed = 1;
        cudaLaunchConfig_t cfg = {};
        cfg.gridDim = dim3(512, 1, 1);
        cfg.blockDim = dim3(256, 1, 1);
        cfg.dynamicSmemBytes = 0;
        cfg.stream = 0;
        cfg.attrs = attr;
        cfg.numAttrs = 1;
        cudaLaunchKernelEx(&cfg, combine_kernel, out);
    }
}

// round 15
// speedup vs baseline: 1.1576x; 1.1576x over previous
#include <cuda_runtime.h>

#define BB 64
#define WW 128
#define FF 64
#define OUTF 64
#define CH 128
#define TI 16
#define PARTN (BB * WW * OUTF)

typedef unsigned long long ull;

// Scratch: projected fsrc (chunk-swizzled), per-head partial outputs
__device__ float g_fsrc[BB * WW * CH];
__device__ float g_part[2 * PARTN];

// ---- packed f32x2 helpers ----
__device__ __forceinline__ ull fma2(ull a, ull b, ull c) {
    ull d; asm("fma.rn.f32x2 %0, %1, %2, %3;" : "=l"(d) : "l"(a), "l"(b), "l"(c)); return d;
}
__device__ __forceinline__ ull add2(ull a, ull b) {
    ull d; asm("add.rn.f32x2 %0, %1, %2;" : "=l"(d) : "l"(a), "l"(b)); return d;
}
__device__ __forceinline__ float lo2(ull v) { return __uint_as_float((unsigned)(v & 0xffffffffu)); }
__device__ __forceinline__ float hi2(ull v) { return __uint_as_float((unsigned)(v >> 32)); }
__device__ __forceinline__ float hsum2(ull v) { return lo2(v) + hi2(v); }
#define ABSMASK 0x7fffffff7fffffffULL

// 16B-chunk swizzle within a 64-float (16-chunk) row
__device__ __forceinline__ int swz16(int row, int c) { return (c & 8) | ((c ^ row) & 7); }

__device__ __forceinline__ unsigned to_tf32(float v) {
    unsigned o; asm("cvt.rna.tf32.f32 %0, %1;" : "=r"(o) : "f"(v)); return o;
}

__device__ __forceinline__ unsigned smem_u32(const void* p) {
    unsigned a;
    asm("{ .reg .u64 t; cvta.to.shared.u64 t, %1; cvt.u32.u64 %0, t; }"
        : "=r"(a) : "l"(p));
    return a;
}
__device__ __forceinline__ void cp_async16(unsigned dst_smem, const void* src) {
    asm volatile("cp.async.cg.shared.global [%0], [%1], 16;"
                 :: "r"(dst_smem), "l"(src) : "memory");
}
__device__ __forceinline__ void cp_async_commit_wait_all() {
    asm volatile("cp.async.commit_group;" ::: "memory");
    asm volatile("cp.async.wait_group 0;" ::: "memory");
}

#define MMA_TF32(acc, a0, a1, a2, a3, b0, b1) \
    asm("mma.sync.aligned.m16n8k8.row.col.f32.tf32.tf32.f32 " \
        "{%0,%1,%2,%3}, {%4,%5,%6,%7}, {%8,%9}, {%0,%1,%2,%3};" \
        : "+f"((acc)[0]), "+f"((acc)[1]), "+f"((acc)[2]), "+f"((acc)[3]) \
        : "r"(a0), "r"(a1), "r"(a2), "r"(a3), "r"(b0), "r"(b1))

// ---------------------------------------------------------------------------
// Kernel 1: fsrc-ONLY projection via tf32 tensor cores, 64-row tiles.
// g_fsrc[8192 x 128] = X @ W_src^T + b_src, stored CHUNK-SWIZZLED per head.
// grid (2, 128): bx = 64-col half of W_src, by = 64-row tile. 256 thr.
// ---------------------------------------------------------------------------
#define PROJ_SM_BYTES ((64 * 68 + 64 * 68) * 4)

__global__ __launch_bounds__(256, 4) void proj_kernel(
    const float* __restrict__ x,
    const float* __restrict__ w_src, const float* __restrict__ b_src)
{
    extern __shared__ unsigned psm[];
    unsigned* xs = psm;                 // 64 x 68 (tf32 bits, RNE)
    unsigned* ws = psm + 64 * 68;       // 64 x 68

    const int tid = threadIdx.x;
    const int row0 = blockIdx.y * 64;
    const int obase = blockIdx.x * 64;

    // ---- fill (convert to tf32 with RNE once) ----
    const float4* __restrict__ x4 = (const float4*)(x + row0 * FF);
    const float4* __restrict__ w4 = (const float4*)(w_src + obase * FF);
    #pragma unroll
    for (int t = 0; t < 4; t++) {        // 1024 float4 of x
        int m = tid + 256 * t;
        int r = m >> 4, c4 = m & 15;
        float4 v = x4[m];
        uint4 u;
        u.x = to_tf32(v.x); u.y = to_tf32(v.y);
        u.z = to_tf32(v.z); u.w = to_tf32(v.w);
        *(uint4*)(xs + r * 68 + c4 * 4) = u;
    }
    #pragma unroll
    for (int t = 0; t < 4; t++) {        // 1024 float4 of w
        int m = tid + 256 * t;
        int r = m >> 4, c4 = m & 15;
        float4 v = w4[m];
        uint4 u;
        u.x = to_tf32(v.x); u.y = to_tf32(v.y);
        u.z = to_tf32(v.z); u.w = to_tf32(v.w);
        *(uint4*)(ws + r * 68 + c4 * 4) = u;
    }
    __syncthreads();

    const int w    = tid >> 5;
    const int lane = tid & 31;
    const int ly = lane >> 2;     // 0..7
    const int lx = lane & 3;      // 0..3
    const int m0 = (w & 3) * 16;
    const int n0 = (w >> 2) * 32;

    float acc[4][4];
    #pragma unroll
    for (int t = 0; t < 4; t++)
        #pragma unroll
        for (int q = 0; q < 4; q++) acc[t][q] = 0.0f;

    #pragma unroll
    for (int k0 = 0; k0 < 64; k0 += 8) {
        unsigned a0 = xs[(m0 + ly) * 68 + k0 + lx];
        unsigned a1 = xs[(m0 + ly + 8) * 68 + k0 + lx];
        unsigned a2 = xs[(m0 + ly) * 68 + k0 + lx + 4];
        unsigned a3 = xs[(m0 + ly + 8) * 68 + k0 + lx + 4];
        #pragma unroll
        for (int t = 0; t < 4; t++) {
            unsigned b0 = ws[(n0 + t * 8 + ly) * 68 + k0 + lx];
            unsigned b1 = ws[(n0 + t * 8 + ly) * 68 + k0 + lx + 4];
            MMA_TF32(acc[t], a0, a1, a2, a3, b0, b1);
        }
    }

    // ---- epilogue: bias + swizzled store into g_fsrc ----
    #pragma unroll
    for (int t = 0; t < 4; t++) {
        int cloc = n0 + t * 8 + 2 * lx;          // local col (pair base), even
        float2 bias = *(const float2*)(b_src + obase + cloc);
        int oloc = obase + cloc;                 // channel 0..127
        int rA = row0 + m0 + ly;                 // bw row (j = rA & 127)
        float2 oA = make_float2(acc[t][0] + bias.x, acc[t][1] + bias.y);
        float2 oB = make_float2(acc[t][2] + bias.x, acc[t][3] + bias.y);
        int hh = oloc >> 6, cc = (oloc & 63) >> 2, fr = oloc & 3;
        int jA = rA & 127, jB = (rA + 8) & 127;
        *(float2*)(g_fsrc + rA * CH + hh * 64 + swz16(jA, cc) * 4 + fr) = oA;
        *(float2*)(g_fsrc + (rA + 8) * CH + hh * 64 + swz16(jB, cc) * 4 + fr) = oB;
    }

#if __CUDA_ARCH__ >= 900
    cudaTriggerProgrammaticLaunchCompletion();
#endif
}

// ---------------------------------------------------------------------------
// Kernel 2: attention + FUSED fdst projection. grid (8, 64, 2), 256 threads.
// fdst (block-exclusive 16x64) is projected IN-KERNEL before the PDL sync:
//   A = X-dst tile (cp.async, smem), B = w_dst via to_tf32(LDG) (L2-hot).
// Then fsrc identity cp.async fill, dots, score, softmax, MMA aggregation.
// smem (floats):
//   fssm   [128 x 64]  swizzled fsrc            0 .. 8192
//   fdsm   [16 x 68]   X-dst -> fdst         8192 .. 9280
//   alphaT [16 x 132]  tf32 bits             9280 .. 11392
//   a04    [64]                             11392
//   sA     [128]                            11456
//   dA     [16]                             11584
// ---------------------------------------------------------------------------
#define OFF_FDST   8192
#define OFF_ALPHAT 9280
#define OFF_A04    11392
#define OFF_SA     11456
#define OFF_DA     11584
#define SM_FLOATS  11600
#define SM_BYTES   (SM_FLOATS * 4)

__global__ __launch_bounds__(256, 4) void attn_kernel(
    const float* __restrict__ x,
    const float* __restrict__ w_dst, const float* __restrict__ b_dst,
    const float* __restrict__ attn_w)
{
    extern __shared__ float sm[];
    float*    fssm   = sm;
    float*    fdsm   = sm + OFF_FDST;
    unsigned* alphaT = (unsigned*)(sm + OFF_ALPHAT);
    float*    a04    = sm + OFF_A04;
    float*    sA     = sm + OFF_SA;
    float*    dA     = sm + OFF_DA;

    const int tid = threadIdx.x;
    const int b  = blockIdx.y;
    const int i0 = blockIdx.x * TI;
    const int h  = blockIdx.z;

    const int w    = tid >> 5;
    const int lane = tid & 31;
    const int ly = lane >> 2;     // 0..7
    const int lx = lane & 3;      // 0..3
    const int jt = tid & 31;

    ulonglong2* fs16 = (ulonglong2*)fssm;

    // ======== PRE-SYNC: fdst projection (independent of proj kernel) ========
    {
        int i = tid >> 4, c = tid & 15;
        cp_async16(smem_u32(fdsm + i * 68 + c * 4),
                   (const float4*)(x + (b * WW + i0 + i) * FF) + c);
    }
    if (tid < 64) a04[tid] = 0.4f * attn_w[h * 64 + tid];
    cp_async_commit_wait_all();
    __syncthreads();

    float accD[4];
    accD[0] = accD[1] = accD[2] = accD[3] = 0.0f;
    {
        const int n0 = w * 8;
        const float* __restrict__ wdh = w_dst + h * 64 * FF + (n0 + ly) * FF;
        #pragma unroll
        for (int k0 = 0; k0 < 64; k0 += 8) {
            unsigned a0 = to_tf32(fdsm[ly * 68 + k0 + lx]);
            unsigned a1 = to_tf32(fdsm[(ly + 8) * 68 + k0 + lx]);
            unsigned a2 = to_tf32(fdsm[ly * 68 + k0 + lx + 4]);
            unsigned a3 = to_tf32(fdsm[(ly + 8) * 68 + k0 + lx + 4]);
            unsigned b0 = to_tf32(wdh[k0 + lx]);
            unsigned b1 = to_tf32(wdh[k0 + lx + 4]);
            MMA_TF32(accD, a0, a1, a2, a3, b0, b1);
        }
    }
    __syncthreads();   // X-dst reads done; fdsm can be overwritten
    {
        const int n0 = w * 8;
        int c = n0 + 2 * lx;
        float2 bias = *(const float2*)(b_dst + h * 64 + c);
        *(float2*)(fdsm + ly * 68 + c) =
            make_float2(accD[0] + bias.x, accD[1] + bias.y);
        *(float2*)(fdsm + (ly + 8) * 68 + c) =
            make_float2(accD[2] + bias.x, accD[3] + bias.y);
    }

    // ======== PDL sync: g_fsrc from proj is now needed ========
#if __CUDA_ARCH__ >= 900
    cudaGridDependencySynchronize();
#endif

    // ---- fill fssm (identity copy, already swizzled) ----
    {
        const float4* __restrict__ g4 = (const float4*)(g_fsrc + b * WW * CH + h * 64);
        #pragma unroll
        for (int t = 0; t < 8; t++) {
            int m = tid + 256 * t;           // 2048 chunks
            int j = m >> 4, c = m & 15;
            cp_async16(smem_u32(fssm + j * 64 + c * 4), g4 + j * 32 + c);
        }
    }
    cp_async_commit_wait_all();
    __syncthreads();   // fssm + fdsm visible

    // ---- per-node dots (1.5-prescaled linear leakyrelu component) ----
    if (tid < 128) {               // sA[j]
        int j = tid;
        const ulonglong2* a16 = (const ulonglong2*)a04;
        ull acc = 0ULL;
        #pragma unroll
        for (int f4 = 0; f4 < 16; f4++) {
            ulonglong2 sv = fs16[j * 16 + swz16(j, f4)];
            ulonglong2 av = a16[f4];
            acc = fma2(av.x, sv.x, acc);
            acc = fma2(av.y, sv.y, acc);
        }
        sA[j] = 1.5f * hsum2(acc);
    } else if (tid < 144) {        // dA[i]
        int il = tid - 128;
        const ulonglong2* d16 = (const ulonglong2*)(fdsm + il * 68);
        const ulonglong2* a16 = (const ulonglong2*)a04;
        ull acc = 0ULL;
        #pragma unroll
        for (int f4 = 0; f4 < 16; f4++) {
            ulonglong2 dv = d16[f4];
            ulonglong2 av = a16[f4];
            acc = fma2(av.x, dv.x, acc);
            acc = fma2(av.y, dv.y, acc);
        }
        dA[il] = 1.5f * hsum2(acc);
    }
    __syncthreads();

    // ---- score: warp w owns i rows {w, w+8}; lanes jt; j = jt + 32c ----
    ull acc2[2][4];
    #pragma unroll
    for (int r = 0; r < 2; r++)
        #pragma unroll
        for (int c = 0; c < 4; c++) acc2[r][c] = 0ULL;

    {
        const ulonglong2* a16 = (const ulonglong2*)a04;
        #pragma unroll 4
        for (int f4 = 0; f4 < 16; f4++) {
            ulonglong2 av = a16[f4];
            ulonglong2 dv[2], sv[4];
            dv[0] = *(const ulonglong2*)(fdsm + w * 68 + f4 * 4);
            dv[1] = *(const ulonglong2*)(fdsm + (w + 8) * 68 + f4 * 4);
            int cs = swz16(jt, f4);
            #pragma unroll
            for (int c = 0; c < 4; c++)
                sv[c] = fs16[(jt + 32 * c) * 16 + cs];
            #pragma unroll
            for (int r = 0; r < 2; r++)
                #pragma unroll
                for (int c = 0; c < 4; c++) {
                    ull t0 = add2(sv[c].x, dv[r].x) & ABSMASK;
                    acc2[r][c] = fma2(av.x, t0, acc2[r][c]);
                    ull t1 = add2(sv[c].y, dv[r].y) & ABSMASK;
                    acc2[r][c] = fma2(av.y, t1, acc2[r][c]);
                }
        }
    }

    // ---- softmax over j (in-warp, no max-sub: |e| <~ 25 << 88) ----
    {
        float sAv[4];
        #pragma unroll
        for (int c = 0; c < 4; c++) sAv[c] = sA[jt + 32 * c];

        #pragma unroll
        for (int r = 0; r < 2; r++) {
            int il = w + 8 * r;
            float dv = dA[il];
            float p[4], ssum = 0.0f;
            #pragma unroll
            for (int c = 0; c < 4; c++) {
                p[c] = __expf(sAv[c] + dv + hsum2(acc2[r][c]));
                ssum += p[c];
            }
            #pragma unroll
            for (int off = 16; off > 0; off >>= 1)
                ssum += __shfl_xor_sync(0xffffffffu, ssum, off);

            float inv = 1.0f / ssum;
            #pragma unroll
            for (int c = 0; c < 4; c++)
                alphaT[il * 132 + jt + 32 * c] = to_tf32(p[c] * inv);
        }
    }
    __syncthreads();

    // ---- aggregation via tf32 MMA: warp w -> n-tile cols [w*8, w*8+8) ----
    {
        const int n0 = w * 8;
        float acc[4];
        acc[0] = acc[1] = acc[2] = acc[3] = 0.0f;

        const int f  = n0 + ly;
        const int cc = f >> 2;
        const int fr = f & 3;

        #pragma unroll
        for (int k0 = 0; k0 < 128; k0 += 8) {
            unsigned a0 = alphaT[ly * 132 + k0 + lx];
            unsigned a1 = alphaT[(ly + 8) * 132 + k0 + lx];
            unsigned a2 = alphaT[ly * 132 + k0 + lx + 4];
            unsigned a3 = alphaT[(ly + 8) * 132 + k0 + lx + 4];
            int j0 = k0 + lx, j1 = k0 + lx + 4;
            unsigned b0 = to_tf32(fssm[j0 * 64 + swz16(j0, cc) * 4 + fr]);
            unsigned b1 = to_tf32(fssm[j1 * 64 + swz16(j1, cc) * 4 + fr]);
            MMA_TF32(acc, a0, a1, a2, a3, b0, b1);
        }

        float* part = g_part + h * PARTN;
        int iA = i0 + ly;
        *(float2*)(part + (b * WW + iA) * OUTF + n0 + 2 * lx) =
            make_float2(acc[0], acc[1]);
        *(float2*)(part + (b * WW + iA + 8) * OUTF + n0 + 2 * lx) =
            make_float2(acc[2], acc[3]);
    }

#if __CUDA_ARCH__ >= 900
    cudaTriggerProgrammaticLaunchCompletion();
#endif
}

// ---------------------------------------------------------------------------
// Kernel 3: combine heads. out = 0.5 * (part0 + part1). 512 x 256 float4.
// ---------------------------------------------------------------------------
__global__ __launch_bounds__(256) void combine_kernel(float* __restrict__ out)
{
    int m = blockIdx.x * 256 + threadIdx.x;
#if __CUDA_ARCH__ >= 900
    cudaGridDependencySynchronize();
#endif
    const float4* p0 = (const float4*)g_part;
    const float4* p1 = (const float4*)(g_part + PARTN);
    float4 a = p0[m], c = p1[m];
    float4 o;
    o.x = 0.5f * (a.x + c.x);
    o.y = 0.5f * (a.y + c.y);
    o.z = 0.5f * (a.z + c.z);
    o.w = 0.5f * (a.w + c.w);
    ((float4*)out)[m] = o;
}

// ---------------------------------------------------------------------------
extern "C" void kernel_launch(void* const* d_in, const int* in_sizes, int n_in,
                              void* d_out, int out_size)
{
    (void)in_sizes; (void)n_in; (void)out_size;
    const float* x      = (const float*)d_in[0];
    const float* w_src  = (const float*)d_in[1];
    const float* b_src  = (const float*)d_in[2];
    const float* w_dst  = (const float*)d_in[3];
    const float* b_dst  = (const float*)d_in[4];
    const float* attn_w = (const float*)d_in[5];
    float* out = (float*)d_out;

    cudaFuncSetAttribute(proj_kernel,
                         cudaFuncAttributeMaxDynamicSharedMemorySize,
                         PROJ_SM_BYTES);
    cudaFuncSetAttribute(attn_kernel,
                         cudaFuncAttributeMaxDynamicSharedMemorySize,
                         SM_BYTES);

    proj_kernel<<<dim3(2, 128), 256, PROJ_SM_BYTES>>>(x, w_src, b_src);

    // attn with PDL edge to proj
    {
        cudaLaunchAttribute attr[1];
        attr[0].id = cudaLaunchAttributeProgrammaticStreamSerialization;
        attr[0].val.programmaticStreamSerializationAllowed = 1;
        cudaLaunchConfig_t cfg = {};
        cfg.gridDim = dim3(WW / TI, BB, 2);
        cfg.blockDim = dim3(256, 1, 1);
        cfg.dynamicSmemBytes = SM_BYTES;
        cfg.stream = 0;
        cfg.attrs = attr;
        cfg.numAttrs = 1;
        cudaLaunchKernelEx(&cfg, attn_kernel, x, w_dst, b_dst, attn_w);
    }

    // combine with PDL edge to attn
    {
        cudaLaunchAttribute attr[1];
        attr[0].id = cudaLaunchAttributeProgrammaticStreamSerialization;
        attr[0].val.programmaticStreamSerializationAllowed = 1;
        cudaLaunchConfig_t cfg = {};
        cfg.gridDim = dim3(512, 1, 1);
        cfg.blockDim = dim3(256, 1, 1);
        cfg.dynamicSmemBytes = 0;
        cfg.stream = 0;
        cfg.attrs = attr;
        cfg.numAttrs = 1;
        cudaLaunchKernelEx(&cfg, combine_kernel, out);
    }
}

// round 16
// speedup vs baseline: 1.2218x; 1.0555x over previous
#include <cuda_runtime.h>

#define BB 64
#define WW 128
#define FF 64
#define OUTF 64
#define CH 128
#define TI 16
#define PARTN (BB * WW * OUTF)

typedef unsigned long long ull;

// Scratch: projected features (with bias; fsrc stored chunk-swizzled), partials
__device__ float g_fsrc[BB * WW * CH];
__device__ float g_fdst[BB * WW * CH];
__device__ float g_part[2 * PARTN];

// ---- packed f32x2 helpers ----
__device__ __forceinline__ ull fma2(ull a, ull b, ull c) {
    ull d; asm("fma.rn.f32x2 %0, %1, %2, %3;" : "=l"(d) : "l"(a), "l"(b), "l"(c)); return d;
}
__device__ __forceinline__ ull add2(ull a, ull b) {
    ull d; asm("add.rn.f32x2 %0, %1, %2;" : "=l"(d) : "l"(a), "l"(b)); return d;
}
__device__ __forceinline__ float lo2(ull v) { return __uint_as_float((unsigned)(v & 0xffffffffu)); }
__device__ __forceinline__ float hi2(ull v) { return __uint_as_float((unsigned)(v >> 32)); }
__device__ __forceinline__ float hsum2(ull v) { return lo2(v) + hi2(v); }
#define ABSMASK 0x7fffffff7fffffffULL

// 16B-chunk swizzle within a 64-float (16-chunk) row
__device__ __forceinline__ int swz16(int row, int c) { return (c & 8) | ((c ^ row) & 7); }

__device__ __forceinline__ unsigned to_tf32(float v) {
    unsigned o; asm("cvt.rna.tf32.f32 %0, %1;" : "=r"(o) : "f"(v)); return o;
}

__device__ __forceinline__ unsigned smem_u32(const void* p) {
    unsigned a;
    asm("{ .reg .u64 t; cvta.to.shared.u64 t, %1; cvt.u32.u64 %0, t; }"
        : "=r"(a) : "l"(p));
    return a;
}
__device__ __forceinline__ void cp_async16(unsigned dst_smem, const void* src) {
    asm volatile("cp.async.cg.shared.global [%0], [%1], 16;"
                 :: "r"(dst_smem), "l"(src) : "memory");
}
__device__ __forceinline__ void cp_async_commit_wait_all() {
    asm volatile("cp.async.commit_group;" ::: "memory");
    asm volatile("cp.async.wait_group 0;" ::: "memory");
}

#define MMA_TF32(acc, a0, a1, a2, a3, b0, b1) \
    asm("mma.sync.aligned.m16n8k8.row.col.f32.tf32.tf32.f32 " \
        "{%0,%1,%2,%3}, {%4,%5,%6,%7}, {%8,%9}, {%0,%1,%2,%3};" \
        : "+f"((acc)[0]), "+f"((acc)[1]), "+f"((acc)[2]), "+f"((acc)[3]) \
        : "r"(a0), "r"(a1), "r"(a2), "r"(a3), "r"(b0), "r"(b1))

// ---------------------------------------------------------------------------
// Kernel 1: projections via tf32 tensor cores, 64-row tiles.
// cp.async RAW fp32 fill; cvt.rna.tf32 at fragment load (RNE, bit-identical
// to cvt-at-fill). C[8192 x 256] = X[8192 x 64] @ W^T + bias.
// grid (4, 128): bx = (src/dst, 64-col half), by = 64-row tile. 256 thr.
// fsrc output is written CHUNK-SWIZZLED (attn copies it verbatim).
// ---------------------------------------------------------------------------
#define PROJ_SM_BYTES ((64 * 68 + 64 * 68) * 4)

__global__ __launch_bounds__(256, 4) void proj_kernel(
    const float* __restrict__ x,
    const float* __restrict__ w_src, const float* __restrict__ b_src,
    const float* __restrict__ w_dst, const float* __restrict__ b_dst)
{
    extern __shared__ float psm[];
    float* xs = psm;                 // 64 x 68 (raw fp32)
    float* ws = psm + 64 * 68;       // 64 x 68

    const int tid = threadIdx.x;
    const int ot = blockIdx.x;           // 0..3
    const int row0 = blockIdx.y * 64;
    const bool is_src = (ot < 2);
    const float* __restrict__ wm = is_src ? w_src : w_dst;
    const float* __restrict__ bv = is_src ? b_src : b_dst;
    const int obase = (ot & 1) * 64;

    // ---- fill via cp.async (raw fp32; no register staging) ----
    const float4* __restrict__ x4 = (const float4*)(x + row0 * FF);
    const float4* __restrict__ w4 = (const float4*)(wm + obase * FF);
    #pragma unroll
    for (int t = 0; t < 4; t++) {
        int m = tid + 256 * t;           // 1024 float4 each
        int r = m >> 4, c4 = m & 15;
        cp_async16(smem_u32(xs + r * 68 + c4 * 4), x4 + m);
        cp_async16(smem_u32(ws + r * 68 + c4 * 4), w4 + m);
    }
    cp_async_commit_wait_all();
    __syncthreads();

    const int w    = tid >> 5;
    const int lane = tid & 31;
    const int ly = lane >> 2;     // 0..7
    const int lx = lane & 3;      // 0..3
    const int m0 = (w & 3) * 16;
    const int n0 = (w >> 2) * 32;

    float acc[4][4];
    #pragma unroll
    for (int t = 0; t < 4; t++)
        #pragma unroll
        for (int q = 0; q < 4; q++) acc[t][q] = 0.0f;

    #pragma unroll
    for (int k0 = 0; k0 < 64; k0 += 8) {
        unsigned a0 = to_tf32(xs[(m0 + ly) * 68 + k0 + lx]);
        unsigned a1 = to_tf32(xs[(m0 + ly + 8) * 68 + k0 + lx]);
        unsigned a2 = to_tf32(xs[(m0 + ly) * 68 + k0 + lx + 4]);
        unsigned a3 = to_tf32(xs[(m0 + ly + 8) * 68 + k0 + lx + 4]);
        #pragma unroll
        for (int t = 0; t < 4; t++) {
            unsigned b0 = to_tf32(ws[(n0 + t * 8 + ly) * 68 + k0 + lx]);
            unsigned b1 = to_tf32(ws[(n0 + t * 8 + ly) * 68 + k0 + lx + 4]);
            MMA_TF32(acc[t], a0, a1, a2, a3, b0, b1);
        }
    }

    // ---- epilogue: bias + store; fsrc goes out chunk-swizzled ----
    float* __restrict__ dst = is_src ? g_fsrc : g_fdst;
    #pragma unroll
    for (int t = 0; t < 4; t++) {
        int cloc = n0 + t * 8 + 2 * lx;          // local col (pair base), even
        float2 bias = *(const float2*)(bv + obase + cloc);
        int oloc = obase + cloc;                 // channel 0..127
        int rA = row0 + m0 + ly;                 // bw row (j = rA & 127)
        float2 oA = make_float2(acc[t][0] + bias.x, acc[t][1] + bias.y);
        float2 oB = make_float2(acc[t][2] + bias.x, acc[t][3] + bias.y);
        if (is_src) {
            int hh = oloc >> 6, cc = (oloc & 63) >> 2, fr = oloc & 3;
            int jA = rA & 127, jB = (rA + 8) & 127;
            *(float2*)(dst + rA * CH + hh * 64 + swz16(jA, cc) * 4 + fr) = oA;
            *(float2*)(dst + (rA + 8) * CH + hh * 64 + swz16(jB, cc) * 4 + fr) = oB;
        } else {
            *(float2*)(dst + rA * CH + oloc) = oA;
            *(float2*)(dst + (rA + 8) * CH + oloc) = oB;
        }
    }

#if __CUDA_ARCH__ >= 900
    cudaTriggerProgrammaticLaunchCompletion();
#endif
}

// ---------------------------------------------------------------------------
// Kernel 2: attention, HEAD-SPLIT. grid (8 i-tiles, 64 b, 2 h), 256 threads.
// Fill: identity cp.async (g_fsrc already swizzled). Score/softmax as r13.
// Aggregation: tf32 MMA, B-fragments via cvt.rna (RNE) from smem fp32.
// smem (floats):
//   fssm   [128 x 64]  swizzled fsrc            0 .. 8192
//   fdsm   [16 x 68]   padded                8192 .. 9280
//   alphaT [16 x 132]  tf32 bits             9280 .. 11392
//   a04    [64]                             11392
//   sA     [128]                            11456
//   dA     [16]                             11584
// ---------------------------------------------------------------------------
#define OFF_FDST   8192
#define OFF_ALPHAT 9280
#define OFF_A04    11392
#define OFF_SA     11456
#define OFF_DA     11584
#define SM_FLOATS  11600
#define SM_BYTES   (SM_FLOATS * 4)

__global__ __launch_bounds__(256, 4) void attn_kernel(const float* __restrict__ attn_w)
{
    extern __shared__ float sm[];
    float*    fssm   = sm;
    float*    fdsm   = sm + OFF_FDST;
    unsigned* alphaT = (unsigned*)(sm + OFF_ALPHAT);
    float*    a04    = sm + OFF_A04;
    float*    sA     = sm + OFF_SA;
    float*    dA     = sm + OFF_DA;

    const int tid = threadIdx.x;
    const int b  = blockIdx.y;
    const int i0 = blockIdx.x * TI;
    const int h  = blockIdx.z;

    ulonglong2* fs16 = (ulonglong2*)fssm;

    // non-dependent input load first (overlaps with proj tail under PDL)
    float a04v = (tid < 64) ? attn_w[h * 64 + tid] : 0.0f;

#if __CUDA_ARCH__ >= 900
    cudaGridDependencySynchronize();    // proj results now visible
#endif

    // ---- fill fssm (identity copy, already swizzled) + fdsm via cp.async
    {
        const float4* __restrict__ g4 = (const float4*)(g_fsrc + b * WW * CH + h * 64);
        #pragma unroll
        for (int t = 0; t < 8; t++) {
            int m = tid + 256 * t;           // 2048 chunks
            int j = m >> 4, c = m & 15;
            cp_async16(smem_u32(fssm + j * 64 + c * 4), g4 + j * 32 + c);
        }
        const float4* __restrict__ g4d = (const float4*)(g_fdst + (b * WW + i0) * CH + h * 64);
        int i = tid >> 4, c = tid & 15;
        cp_async16(smem_u32(fdsm + i * 68 + c * 4), g4d + i * 32 + c);
    }
    if (tid < 64) a04[tid] = 0.4f * a04v;
    cp_async_commit_wait_all();
    __syncthreads();

    // ---- per-node dots (1.5-prescaled linear leakyrelu component) ----
    if (tid < 128) {               // sA[j]
        int j = tid;
        const ulonglong2* a16 = (const ulonglong2*)a04;
        ull acc = 0ULL;
        #pragma unroll
        for (int f4 = 0; f4 < 16; f4++) {
            ulonglong2 sv = fs16[j * 16 + swz16(j, f4)];
            ulonglong2 av = a16[f4];
            acc = fma2(av.x, sv.x, acc);
            acc = fma2(av.y, sv.y, acc);
        }
        sA[j] = 1.5f * hsum2(acc);
    } else if (tid < 144) {        // dA[i]
        int il = tid - 128;
        const ulonglong2* d16 = (const ulonglong2*)(fdsm + il * 68);
        const ulonglong2* a16 = (const ulonglong2*)a04;
        ull acc = 0ULL;
        #pragma unroll
        for (int f4 = 0; f4 < 16; f4++) {
            ulonglong2 dv = d16[f4];
            ulonglong2 av = a16[f4];
            acc = fma2(av.x, dv.x, acc);
            acc = fma2(av.y, dv.y, acc);
        }
        dA[il] = 1.5f * hsum2(acc);
    }
    __syncthreads();

    // ---- score: warp w owns i rows {w, w+8}; lanes jt; j = jt + 32c ----
    const int jt = tid & 31;
    const int w  = tid >> 5;

    ull acc2[2][4];
    #pragma unroll
    for (int r = 0; r < 2; r++)
        #pragma unroll
        for (int c = 0; c < 4; c++) acc2[r][c] = 0ULL;

    {
        const ulonglong2* a16 = (const ulonglong2*)a04;
        #pragma unroll 4
        for (int f4 = 0; f4 < 16; f4++) {
            ulonglong2 av = a16[f4];
            ulonglong2 dv[2], sv[4];
            dv[0] = *(const ulonglong2*)(fdsm + w * 68 + f4 * 4);
            dv[1] = *(const ulonglong2*)(fdsm + (w + 8) * 68 + f4 * 4);
            int cs = swz16(jt, f4);
            #pragma unroll
            for (int c = 0; c < 4; c++)
                sv[c] = fs16[(jt + 32 * c) * 16 + cs];
            #pragma unroll
            for (int r = 0; r < 2; r++)
                #pragma unroll
                for (int c = 0; c < 4; c++) {
                    ull t0 = add2(sv[c].x, dv[r].x) & ABSMASK;
                    acc2[r][c] = fma2(av.x, t0, acc2[r][c]);
                    ull t1 = add2(sv[c].y, dv[r].y) & ABSMASK;
                    acc2[r][c] = fma2(av.y, t1, acc2[r][c]);
                }
        }
    }

    // ---- softmax over j (in-warp, no max-sub: |e| <~ 25 << 88) ----
    {
        float sAv[4];
        #pragma unroll
        for (int c = 0; c < 4; c++) sAv[c] = sA[jt + 32 * c];

        #pragma unroll
        for (int r = 0; r < 2; r++) {
            int il = w + 8 * r;
            float dv = dA[il];
            float p[4], ssum = 0.0f;
            #pragma unroll
            for (int c = 0; c < 4; c++) {
                p[c] = __expf(sAv[c] + dv + hsum2(acc2[r][c]));
                ssum += p[c];
            }
            #pragma unroll
            for (int off = 16; off > 0; off >>= 1)
                ssum += __shfl_xor_sync(0xffffffffu, ssum, off);

            float inv = 1.0f / ssum;
            #pragma unroll
            for (int c = 0; c < 4; c++)
                alphaT[il * 132 + jt + 32 * c] = to_tf32(p[c] * inv);
        }
    }
    __syncthreads();

    // ---- aggregation via tf32 MMA: warp w -> n-tile cols [w*8, w*8+8) ----
    {
        const int lane = tid & 31;
        const int ly = lane >> 2;     // 0..7
        const int lx = lane & 3;      // 0..3
        const int n0 = w * 8;

        float acc[4];
        acc[0] = acc[1] = acc[2] = acc[3] = 0.0f;

        const int f  = n0 + ly;
        const int cc = f >> 2;
        const int fr = f & 3;

        #pragma unroll
        for (int k0 = 0; k0 < 128; k0 += 8) {
            unsigned a0 = alphaT[ly * 132 + k0 + lx];
            unsigned a1 = alphaT[(ly + 8) * 132 + k0 + lx];
            unsigned a2 = alphaT[ly * 132 + k0 + lx + 4];
            unsigned a3 = alphaT[(ly + 8) * 132 + k0 + lx + 4];
            int j0 = k0 + lx, j1 = k0 + lx + 4;
            unsigned b0 = to_tf32(fssm[j0 * 64 + swz16(j0, cc) * 4 + fr]);
            unsigned b1 = to_tf32(fssm[j1 * 64 + swz16(j1, cc) * 4 + fr]);
            MMA_TF32(acc, a0, a1, a2, a3, b0, b1);
        }

        float* part = g_part + h * PARTN;
        int iA = i0 + ly;
        *(float2*)(part + (b * WW + iA) * OUTF + n0 + 2 * lx) =
            make_float2(acc[0], acc[1]);
        *(float2*)(part + (b * WW + iA + 8) * OUTF + n0 + 2 * lx) =
            make_float2(acc[2], acc[3]);
    }

#if __CUDA_ARCH__ >= 900
    cudaTriggerProgrammaticLaunchCompletion();
#endif
}

// ---------------------------------------------------------------------------
// Kernel 3: combine heads. out = 0.5 * (part0 + part1). 512 x 256 float4.
// ---------------------------------------------------------------------------
__global__ __launch_bounds__(256) void combine_kernel(float* __restrict__ out)
{
    int m = blockIdx.x * 256 + threadIdx.x;
#if __CUDA_ARCH__ >= 900
    cudaGridDependencySynchronize();
#endif
    const float4* p0 = (const float4*)g_part;
    const float4* p1 = (const float4*)(g_part + PARTN);
    float4 a = p0[m], c = p1[m];
    float4 o;
    o.x = 0.5f * (a.x + c.x);
    o.y = 0.5f * (a.y + c.y);
    o.z = 0.5f * (a.z + c.z);
    o.w = 0.5f * (a.w + c.w);
    ((float4*)out)[m] = o;
}

// ---------------------------------------------------------------------------
extern "C" void kernel_launch(void* const* d_in, const int* in_sizes, int n_in,
                              void* d_out, int out_size)
{
    (void)in_sizes; (void)n_in; (void)out_size;
    const float* x      = (const float*)d_in[0];
    const float* w_src  = (const float*)d_in[1];
    const float* b_src  = (const float*)d_in[2];
    const float* w_dst  = (const float*)d_in[3];
    const float* b_dst  = (const float*)d_in[4];
    const float* attn_w = (const float*)d_in[5];
    float* out = (float*)d_out;

    cudaFuncSetAttribute(proj_kernel,
                         cudaFuncAttributeMaxDynamicSharedMemorySize,
                         PROJ_SM_BYTES);
    cudaFuncSetAttribute(attn_kernel,
                         cudaFuncAttributeMaxDynamicSharedMemorySize,
                         SM_BYTES);

    proj_kernel<<<dim3(4, 128), 256, PROJ_SM_BYTES>>>(x, w_src, b_src, w_dst, b_dst);

    // attn with PDL edge to proj
    {
        cudaLaunchAttribute attr[1];
        attr[0].id = cudaLaunchAttributeProgrammaticStreamSerialization;
        attr[0].val.programmaticStreamSerializationAllowed = 1;
        cudaLaunchConfig_t cfg = {};
        cfg.gridDim = dim3(WW / TI, BB, 2);
        cfg.blockDim = dim3(256, 1, 1);
        cfg.dynamicSmemBytes = SM_BYTES;
        cfg.stream = 0;
        cfg.attrs = attr;
        cfg.numAttrs = 1;
        cudaLaunchKernelEx(&cfg, attn_kernel, attn_w);
    }

    // combine with PDL edge to attn
    {
        cudaLaunchAttribute attr[1];
        attr[0].id = cudaLaunchAttributeProgrammaticStreamSerialization;
        attr[0].val.programmaticStreamSerializationAllowed = 1;
        cudaLaunchConfig_t cfg = {};
        cfg.gridDim = dim3(512, 1, 1);
        cfg.blockDim = dim3(256, 1, 1);
        cfg.dynamicSmemBytes = 0;
        cfg.stream = 0;
        cfg.attrs = attr;
        cfg.numAttrs = 1;
        cudaLaunchKernelEx(&cfg, combine_kernel, out);
    }
}